// round 13
// baseline (speedup 1.0000x reference)
#include <cuda_runtime.h>
#include <cstdint>

#define TT 2048
#define BB 32
#define NN 1024
#define NCH 32   // 64-t chunks

// ---------------- scratch (device globals; no allocation allowed) ----------
__device__ float g_dec_acc[BB * NN];       // atomic accumulator for dec gemm
__device__ float g_oacc  [BB * NN];        // atomic accumulator for output gemm
__device__ float g_dec   [BB * NN];        // dec_feature (combined)
__device__ float g_scores[BB * TT];
__device__ float g_content[BB * NN];       // UNNORMALIZED content (atomics)
__device__ float g_den   [BB];             // softmax denominators (atomics)
__device__ int   g_ctr0;                   // dec gemm blocks done (kernel A)
__device__ int   g_ctr2;                   // fct gemm blocks done (kernel D)
__device__ int   g_ctr3;                   // out blocks done (kernel D reset)

__device__ __forceinline__ float fast_tanh(float x) {      // precise (~1e-7)
    float e = __expf(2.0f * x);
    return 1.0f - __fdividef(2.0f, e + 1.0f);
}
__device__ __forceinline__ float tanh_mufu(float x) {      // MUFU.TANH, 1 op
    float y;
    asm("tanh.approx.f32 %0, %1;" : "=f"(y) : "f"(x));
    return y;
}

#define KC 64
#define QK (KC / 4)
#define PITCH (KC + 4)

// ---------------------------------------------------------------------------
// GEMM tile body with atomic output: acc_out[b,n] += sum_{k chunk} S[b,k]W[n,k]
// Tile 32b x 64n x 64k, thread tile 2b x 4n. If norm, S rows scaled by
// 1/g_den[row] on load (row == batch index).
// ---------------------------------------------------------------------------
__device__ __forceinline__ void gemm_tile_atomic(
    const float* __restrict__ Sp, const float* __restrict__ Wp,
    int ws, int col0, int k0, int n0, float* acc_out,
    float* sS, float* sW, int tid, bool norm)
{
    #pragma unroll
    for (int p = 0; p < 2; p++) {
        int i = tid + p * 256;
        int row = i >> 4, q = i & 15;
        float4 v = *(const float4*)&Sp[row * NN + k0 + q * 4];
        if (norm) {
            float inv = __fdividef(1.0f, g_den[row]);
            v.x *= inv; v.y *= inv; v.z *= inv; v.w *= inv;
        }
        *(float4*)&sS[row * PITCH + q * 4] = v;
    }
    #pragma unroll
    for (int p = 0; p < 4; p++) {
        int i = tid + p * 256;
        int row = i >> 4, q = i & 15;
        float4 v = *(const float4*)&Wp[(size_t)(n0 + row) * ws + col0 + q * 4];
        *(float4*)&sW[row * PITCH + q * 4] = v;
    }
    __syncthreads();

    const int b0 = (tid & 15) * 2;
    const int nl = (tid >> 4) * 4;
    float acc[2][4];
    #pragma unroll
    for (int i = 0; i < 2; i++)
        #pragma unroll
        for (int j = 0; j < 4; j++) acc[i][j] = 0.f;

    const float* ps = sS + b0 * PITCH;
    const float* pw = sW + nl * PITCH;
    #pragma unroll 4
    for (int k4 = 0; k4 < QK; k4++) {
        float4 s[2], w[4];
        #pragma unroll
        for (int i = 0; i < 2; i++) s[i] = *(const float4*)(ps + i * PITCH + k4 * 4);
        #pragma unroll
        for (int j = 0; j < 4; j++) w[j] = *(const float4*)(pw + j * PITCH + k4 * 4);
        #pragma unroll
        for (int i = 0; i < 2; i++)
            #pragma unroll
            for (int j = 0; j < 4; j++)
                acc[i][j] += s[i].x * w[j].x + s[i].y * w[j].y
                           + s[i].z * w[j].z + s[i].w * w[j].w;
    }

    #pragma unroll
    for (int i = 0; i < 2; i++) {
        float* dst = acc_out + (b0 + i) * NN + n0 + nl;
        #pragma unroll
        for (int j = 0; j < 4; j++) atomicAdd(dst + j, acc[i][j]);
    }
}

__device__ __forceinline__ void spin_wait(int* ctr, int target, int tid,
                                          int* s_flag)
{
    if (tid == 0) {
        while (atomicAdd(ctr, 0) < target) __nanosleep(200);
        *s_flag = 1;
    }
    __syncthreads();
    __threadfence();   // acquire
}

// ---------------------------------------------------------------------------
// KERNEL A (640 blocks, all co-resident):
//   bid <256 : dec gemm (hx @ Ws_w +-> g_dec_acc), signal g_ctr0
//   256..511 : hx-half gemm (hx @ lin_w[:,NN:] +-> g_oacc)  [consumed by D]
//   512..639 : zero g_content/g_den (overlapped); spin; g_dec = acc + Ws_b;
//              re-zero g_dec_acc for next replay.
// ---------------------------------------------------------------------------
__global__ __launch_bounds__(256) void kernelA(
    const float* __restrict__ hx,
    const float* __restrict__ Ws_w,
    const float* __restrict__ lin_w,
    const float* __restrict__ Ws_b)
{
    __shared__ float sS[32 * PITCH];
    __shared__ float sW[64 * PITCH];
    __shared__ int   s_flag;
    const int bid = blockIdx.x;
    const int tid = threadIdx.x;

    if (bid < 512) {
        const int rem = bid & 255;
        const int n0  = (rem & 15) * 64;
        const int k0  = (rem >> 4) * KC;
        if (bid < 256) {
            gemm_tile_atomic(hx, Ws_w, NN, k0, k0, n0, g_dec_acc, sS, sW, tid, false);
            __threadfence();
            __syncthreads();
            if (tid == 0) atomicAdd(&g_ctr0, 1);
        } else {
            gemm_tile_atomic(hx, lin_w, 2 * NN, NN + k0, k0, n0, g_oacc, sS, sW, tid, false);
        }
    } else {
        const int i = (bid - 512) * 256 + tid;     // 0..32767
        g_content[i] = 0.f;
        if (i < BB) g_den[i] = 0.f;
        spin_wait(&g_ctr0, 256, tid, &s_flag);
        g_dec[i] = g_dec_acc[i] + Ws_b[i & (NN - 1)];
        g_dec_acc[i] = 0.f;
    }
}

// ---------------------------------------------------------------------------
// scores[b,t] = sum_n tanh(ef[t,b,n] + dec[b,n]) * v[n] + vb   (MUFU.TANH)
// ---------------------------------------------------------------------------
__global__ __launch_bounds__(256) void scores_kernel(
    const float* __restrict__ ef, const float* __restrict__ vw,
    const float* __restrict__ vb)
{
    const int b   = blockIdx.y;
    const int t0  = blockIdx.x * 16;
    const int tid = threadIdx.x;
    __shared__ float sred[16 * 256];

    float4 d = reinterpret_cast<const float4*>(g_dec + b * NN)[tid];
    float4 v = reinterpret_cast<const float4*>(vw)[tid];

    float pr[16];
    #pragma unroll
    for (int r = 0; r < 16; r++) {
        size_t row = ((size_t)(t0 + r) * BB + b) * NN;
        float4 x = __ldcs(&reinterpret_cast<const float4*>(ef + row)[tid]);
        pr[r] = tanh_mufu(x.x + d.x) * v.x
              + tanh_mufu(x.y + d.y) * v.y
              + tanh_mufu(x.z + d.z) * v.z
              + tanh_mufu(x.w + d.w) * v.w;
    }
    #pragma unroll
    for (int r = 0; r < 16; r++) sred[r * 256 + tid] = pr[r];
    __syncthreads();

    const int warp = tid >> 5, lane = tid & 31;
    #pragma unroll
    for (int rr = 0; rr < 2; rr++) {
        int r = warp * 2 + rr;
        float s = 0.f;
        #pragma unroll
        for (int j = 0; j < 8; j++) s += sred[r * 256 + lane + 32 * j];
        #pragma unroll
        for (int o = 16; o; o >>= 1) s += __shfl_xor_sync(0xffffffffu, s, o);
        if (lane == 0) g_scores[b * TT + t0 + r] = s + vb[0];
    }
}

// ---------------------------------------------------------------------------
// content (C=0 exponentials — scores O(+-5) by construction). Grid
// (NCH+1, BB): ch==NCH blocks PREFETCH lin_w low half into L2 (for kernelD),
// overlapped with the DRAM-saturated stream.
// ---------------------------------------------------------------------------
__global__ __launch_bounds__(256) void content_partial_kernel(
    const float* __restrict__ eo, const float* __restrict__ mask,
    const float* __restrict__ lin_w)
{
    const int b = blockIdx.y, ch = blockIdx.x, tid = threadIdx.x;

    if (ch == NCH) {   // prefetch 32 rows of lin_w[:,0:NN] per b-index block
        const float4* src = reinterpret_cast<const float4*>(
            lin_w + (size_t)(b * 32) * (2 * NN));
        float acc = 0.f;
        #pragma unroll
        for (int p = 0; p < 32; p++) {
            // rows b*32..b*32+31, cols 0..NN: row r quad q (q<NN/4)
            int r = p;                           // 32 rows
            const float4* rp = reinterpret_cast<const float4*>(
                lin_w + (size_t)(b * 32 + r) * (2 * NN));
            float4 v = __ldcg(&rp[tid]);         // 256 thr * 4 = NN floats
            acc += v.x;                          // keep the load alive
        }
        if (acc == 123456789.f) g_scores[0] = acc;  // never true; defeats DCE
        return;
    }

    const int t0 = ch * 64;
    __shared__ float s_w[64];

    if (tid < 64) {
        float e = __expf(g_scores[b * TT + t0 + tid]);
        s_w[tid] = e * mask[b * TT + t0 + tid];
        #pragma unroll
        for (int o = 16; o; o >>= 1) e += __shfl_xor_sync(0xffffffffu, e, o);
        if ((tid & 31) == 0) atomicAdd(&g_den[b], e);
    }
    __syncthreads();

    float4 acc = make_float4(0.f, 0.f, 0.f, 0.f);
    size_t base = (((size_t)t0) * BB + b) * NN;
    #pragma unroll 4
    for (int r = 0; r < 64; r++) {
        float a = s_w[r];
        float4 x = __ldcs(&reinterpret_cast<const float4*>(eo + base + (size_t)r * BB * NN)[tid]);
        acc.x += a * x.x;  acc.y += a * x.y;
        acc.z += a * x.z;  acc.w += a * x.w;
    }
    float* dst = g_content + b * NN + tid * 4;
    atomicAdd(dst + 0, acc.x);
    atomicAdd(dst + 1, acc.y);
    atomicAdd(dst + 2, acc.z);
    atomicAdd(dst + 3, acc.w);
}

// ---------------------------------------------------------------------------
// KERNEL D (384 blocks, co-resident):
//   bid <256 : ct gemm ((g_content/den) @ lin_w[:,0:NN] +-> g_oacc), signal
//   256..383 : spin; out = tanh(g_oacc + lin_b); zero g_oacc; reset counters.
// g_content/g_den/g_oacc referenced in DEVICE code only (host-side
// __device__-symbol args bind the zero ATS shadow on GB300 — R1/R2 bug).
// ---------------------------------------------------------------------------
__global__ __launch_bounds__(256) void kernelD(
    const float* __restrict__ lin_w,
    const float* __restrict__ lin_b,
    float* __restrict__ out)
{
    __shared__ float sS[32 * PITCH];
    __shared__ float sW[64 * PITCH];
    __shared__ int   s_flag;
    const int bid = blockIdx.x;
    const int tid = threadIdx.x;

    if (bid < 256) {
        const int n0 = (bid & 15) * 64;
        const int k0 = (bid >> 4) * KC;
        gemm_tile_atomic(g_content, lin_w, 2 * NN, k0, k0, n0, g_oacc,
                         sS, sW, tid, true);
        __threadfence();
        __syncthreads();
        if (tid == 0) atomicAdd(&g_ctr2, 1);
    } else {
        spin_wait(&g_ctr2, 256, tid, &s_flag);
        const int i = (bid - 256) * 256 + tid;
        out[i] = fast_tanh(g_oacc[i] + lin_b[i & (NN - 1)]);
        g_oacc[i] = 0.f;                 // ready for next graph replay
        __syncthreads();
        if (tid == 0) {
            int old = atomicAdd(&g_ctr3, 1);
            if (old == 127) {            // last finisher resets counters
                g_ctr0 = 0; g_ctr2 = 0; g_ctr3 = 0;
                __threadfence();
            }
        }
    }
}

// ---------------------------------------------------------------------------
extern "C" void kernel_launch(void* const* d_in, const int* in_sizes, int n_in,
                              void* d_out, int out_size)
{
    const float* decoder_hx      = (const float*)d_in[0];
    const float* encoder_outputs = (const float*)d_in[1];
    const float* encoder_feature = (const float*)d_in[2];
    const float* mask_tensor     = (const float*)d_in[3];
    const float* Ws_w            = (const float*)d_in[4];
    const float* Ws_b            = (const float*)d_in[5];
    const float* v_w             = (const float*)d_in[6];
    const float* v_b             = (const float*)d_in[7];
    const float* lin_w           = (const float*)d_in[8];
    const float* lin_b           = (const float*)d_in[9];
    float* out = (float*)d_out;

    // 1) dec gemm + hx-half gemm (atomic accum) + dec combine + zeroing
    kernelA<<<640, 256>>>(decoder_hx, Ws_w, lin_w, Ws_b);

    // 2) scores (streams 256MB)
    scores_kernel<<<dim3(TT / 16, BB), 256>>>(encoder_feature, v_w, v_b);

    // 3) content (streams 256MB) + lin_w L2 prefetch for kernelD
    content_partial_kernel<<<dim3(NCH + 1, BB), 256>>>(
        encoder_outputs, mask_tensor, lin_w);

    // 4) ct gemm (normalized, atomic accum) + output tanh + counter reset
    kernelD<<<384, 256>>>(lin_w, lin_b, out);

    (void)in_sizes; (void)n_in; (void)out_size;
}

// round 14
// speedup vs baseline: 1.0174x; 1.0174x over previous
#include <cuda_runtime.h>
#include <cstdint>

#define TT 2048
#define BB 32
#define NN 1024
#define NCH 32   // 64-t chunks

// ---------------- scratch (device globals; no allocation allowed) ----------
__device__ float g_apart[16u * BB * NN];   // dec split-K partials (16 x 64k)
__device__ float g_fhx  [16u * BB * NN];   // hx @ lin_w[:,NN:] partials
__device__ float g_fct  [16u * BB * NN];   // content_raw @ lin_w[:,:NN] partials
__device__ float g_dec  [BB * NN];         // dec_feature (combined)
__device__ float g_scores[BB * TT];
__device__ float g_content[BB * NN];       // UNNORMALIZED content (atomics)
__device__ float g_den  [BB];              // softmax denominators (atomics)
__device__ int   g_ctr0, g_flag0;          // kernelA producer count / done flag
__device__ int   g_ctr2, g_flag2;          // kernelD producer count / done flag
__device__ int   g_ctr3;                   // kernelD consumer count (reset)

__device__ __forceinline__ float fast_tanh(float x) {      // precise (~1e-7)
    float e = __expf(2.0f * x);
    return 1.0f - __fdividef(2.0f, e + 1.0f);
}
__device__ __forceinline__ float tanh_mufu(float x) {      // MUFU.TANH, 1 op
    float y;
    asm("tanh.approx.f32 %0, %1;" : "=f"(y) : "f"(x));
    return y;
}

#define KC 64
#define QK (KC / 4)
#define PITCH (KC + 4)

// ---------------------------------------------------------------------------
// GEMM tile body: part[kc][b][n] = sum_{k in 64-chunk} S[b][k]*W[n][k]
// Tile 32b x 64n x 64k, thread tile 2b x 4n.
// ---------------------------------------------------------------------------
__device__ __forceinline__ void gemm_tile(
    const float* __restrict__ Sp, const float* __restrict__ Wp,
    int ws, int col0, int k0, int n0, float* outp,
    float* sS, float* sW, int tid)
{
    #pragma unroll
    for (int p = 0; p < 2; p++) {
        int i = tid + p * 256;
        int row = i >> 4, q = i & 15;
        float4 v = *(const float4*)&Sp[row * NN + k0 + q * 4];
        *(float4*)&sS[row * PITCH + q * 4] = v;
    }
    #pragma unroll
    for (int p = 0; p < 4; p++) {
        int i = tid + p * 256;
        int row = i >> 4, q = i & 15;
        float4 v = *(const float4*)&Wp[(size_t)(n0 + row) * ws + col0 + q * 4];
        *(float4*)&sW[row * PITCH + q * 4] = v;
    }
    __syncthreads();

    const int b0 = (tid & 15) * 2;
    const int nl = (tid >> 4) * 4;
    float acc[2][4];
    #pragma unroll
    for (int i = 0; i < 2; i++)
        #pragma unroll
        for (int j = 0; j < 4; j++) acc[i][j] = 0.f;

    const float* ps = sS + b0 * PITCH;
    const float* pw = sW + nl * PITCH;
    #pragma unroll 4
    for (int k4 = 0; k4 < QK; k4++) {
        float4 s[2], w[4];
        #pragma unroll
        for (int i = 0; i < 2; i++) s[i] = *(const float4*)(ps + i * PITCH + k4 * 4);
        #pragma unroll
        for (int j = 0; j < 4; j++) w[j] = *(const float4*)(pw + j * PITCH + k4 * 4);
        #pragma unroll
        for (int i = 0; i < 2; i++)
            #pragma unroll
            for (int j = 0; j < 4; j++)
                acc[i][j] += s[i].x * w[j].x + s[i].y * w[j].y
                           + s[i].z * w[j].z + s[i].w * w[j].w;
    }

    #pragma unroll
    for (int i = 0; i < 2; i++) {
        float4 r = make_float4(acc[i][0], acc[i][1], acc[i][2], acc[i][3]);
        *(float4*)&outp[(b0 + i) * NN + n0 + nl] = r;
    }
}

// Producer completion: count once; the 256th producer raises the flag.
__device__ __forceinline__ void signal_done(int* ctr, int* flag, int tid)
{
    __threadfence();                    // release this block's writes
    __syncthreads();
    if (tid == 0) {
        int old = atomicAdd(ctr, 1);
        if (old == 255) {
            __threadfence();            // order counter obs before flag
            *(volatile int*)flag = 1;
        }
    }
}

// Consumer wait: PLAIN volatile load poll (no atomic ALU contention — the
// R12/R13 atomicAdd(ctr,0) poll storm serialized one LTS slice and poisoned
// the whole merged kernel).
__device__ __forceinline__ void wait_flag(int* flag, int tid, int* s_flag)
{
    if (tid == 0) {
        while (*(volatile int*)flag == 0) __nanosleep(1000);
        *s_flag = 1;
    }
    __syncthreads();
    __threadfence();   // acquire
}

// ---------------------------------------------------------------------------
// KERNEL A (640 blocks, all co-resident — wait is deadlock-free):
//   bid <256 : src0 gemm (hx @ Ws_w -> g_apart), signal ctr0/flag0
//   256..511 : src1 gemm (hx @ lin_w[:,NN:] -> g_fhx)
//   512..639 : zero g_content/g_den (overlapped), wait flag0,
//              then g_dec = Ws_b + sum of 16 partials
// ---------------------------------------------------------------------------
__global__ __launch_bounds__(256) void kernelA(
    const float* __restrict__ hx,
    const float* __restrict__ Ws_w,
    const float* __restrict__ lin_w,
    const float* __restrict__ Ws_b)
{
    __shared__ float sS[32 * PITCH];
    __shared__ float sW[64 * PITCH];
    __shared__ int   s_flag;
    const int bid = blockIdx.x;
    const int tid = threadIdx.x;

    if (bid < 512) {
        const int rem = bid & 255;
        const int n0  = (rem & 15) * 64;
        const int k0  = (rem >> 4) * KC;
        if (bid < 256) {
            gemm_tile(hx, Ws_w, NN, k0, k0, n0,
                      g_apart + (size_t)(rem >> 4) * (BB * NN), sS, sW, tid);
            signal_done(&g_ctr0, &g_flag0, tid);
        } else {
            gemm_tile(hx, lin_w, 2 * NN, NN + k0, k0, n0,
                      g_fhx + (size_t)(rem >> 4) * (BB * NN), sS, sW, tid);
        }
    } else {
        const int i = (bid - 512) * 256 + tid;     // 0..32767
        g_content[i] = 0.f;
        if (i < BB) g_den[i] = 0.f;
        wait_flag(&g_flag0, tid, &s_flag);
        float s = Ws_b[i & (NN - 1)];
        #pragma unroll
        for (int c = 0; c < 16; c++) s += g_apart[c * (BB * NN) + i];
        g_dec[i] = s;
    }
}

// ---------------------------------------------------------------------------
// scores[b,t] = sum_n tanh(ef[t,b,n] + dec[b,n]) * v[n] + vb   (MUFU.TANH)
// ---------------------------------------------------------------------------
__global__ __launch_bounds__(256) void scores_kernel(
    const float* __restrict__ ef, const float* __restrict__ vw,
    const float* __restrict__ vb)
{
    const int b   = blockIdx.y;
    const int t0  = blockIdx.x * 16;
    const int tid = threadIdx.x;
    __shared__ float sred[16 * 256];

    float4 d = reinterpret_cast<const float4*>(g_dec + b * NN)[tid];
    float4 v = reinterpret_cast<const float4*>(vw)[tid];

    float pr[16];
    #pragma unroll
    for (int r = 0; r < 16; r++) {
        size_t row = ((size_t)(t0 + r) * BB + b) * NN;
        float4 x = __ldcs(&reinterpret_cast<const float4*>(ef + row)[tid]);
        pr[r] = tanh_mufu(x.x + d.x) * v.x
              + tanh_mufu(x.y + d.y) * v.y
              + tanh_mufu(x.z + d.z) * v.z
              + tanh_mufu(x.w + d.w) * v.w;
    }
    #pragma unroll
    for (int r = 0; r < 16; r++) sred[r * 256 + tid] = pr[r];
    __syncthreads();

    const int warp = tid >> 5, lane = tid & 31;
    #pragma unroll
    for (int rr = 0; rr < 2; rr++) {
        int r = warp * 2 + rr;
        float s = 0.f;
        #pragma unroll
        for (int j = 0; j < 8; j++) s += sred[r * 256 + lane + 32 * j];
        #pragma unroll
        for (int o = 16; o; o >>= 1) s += __shfl_xor_sync(0xffffffffu, s, o);
        if (lane == 0) g_scores[b * TT + t0 + r] = s + vb[0];
    }
}

// ---------------------------------------------------------------------------
// content (C=0 exponentials — scores O(+-5) by construction):
//   w_t = exp(s_t)*mask_t ; g_den[b] += sum exp(s_t)
//   g_content[b][:] += sum_t w_t * eo[t,b,:]    (RED.ADD)
// ---------------------------------------------------------------------------
__global__ __launch_bounds__(256) void content_partial_kernel(
    const float* __restrict__ eo, const float* __restrict__ mask)
{
    const int b = blockIdx.y, ch = blockIdx.x, tid = threadIdx.x;
    const int t0 = ch * 64;
    __shared__ float s_w[64];

    if (tid < 64) {
        float e = __expf(g_scores[b * TT + t0 + tid]);
        s_w[tid] = e * mask[b * TT + t0 + tid];
        #pragma unroll
        for (int o = 16; o; o >>= 1) e += __shfl_xor_sync(0xffffffffu, e, o);
        if ((tid & 31) == 0) atomicAdd(&g_den[b], e);
    }
    __syncthreads();

    float4 acc = make_float4(0.f, 0.f, 0.f, 0.f);
    size_t base = (((size_t)t0) * BB + b) * NN;
    #pragma unroll 4
    for (int r = 0; r < 64; r++) {
        float a = s_w[r];
        float4 x = __ldcs(&reinterpret_cast<const float4*>(eo + base + (size_t)r * BB * NN)[tid]);
        acc.x += a * x.x;  acc.y += a * x.y;
        acc.z += a * x.z;  acc.w += a * x.w;
    }
    float* dst = g_content + b * NN + tid * 4;
    atomicAdd(dst + 0, acc.x);
    atomicAdd(dst + 1, acc.y);
    atomicAdd(dst + 2, acc.z);
    atomicAdd(dst + 3, acc.w);
}

// ---------------------------------------------------------------------------
// KERNEL D (384 blocks, co-resident):
//   bid <256 : fct gemm (g_content @ lin_w[:,0:NN] -> g_fct), signal ctr2/flag2
//   256..383 : wait flag2; out = tanh(lin_b + sum fhx + sum fct / den);
//              last finisher resets counters+flags for the next graph replay.
// g_content/g_den read in DEVICE code only (host-side __device__-symbol args
// bind the zero ATS shadow on GB300 — R1/R2 bug).
// ---------------------------------------------------------------------------
__global__ __launch_bounds__(256) void kernelD(
    const float* __restrict__ lin_w,
    const float* __restrict__ lin_b,
    float* __restrict__ out)
{
    __shared__ float sS[32 * PITCH];
    __shared__ float sW[64 * PITCH];
    __shared__ int   s_flag;
    const int bid = blockIdx.x;
    const int tid = threadIdx.x;

    if (bid < 256) {
        const int n0 = (bid & 15) * 64;
        const int k0 = (bid >> 4) * KC;
        gemm_tile(g_content, lin_w, 2 * NN, k0, k0, n0,
                  g_fct + (size_t)(bid >> 4) * (BB * NN), sS, sW, tid);
        signal_done(&g_ctr2, &g_flag2, tid);
    } else {
        wait_flag(&g_flag2, tid, &s_flag);
        const int i = (bid - 256) * 256 + tid;
        float shx = lin_b[i & (NN - 1)];
        #pragma unroll
        for (int c = 0; c < 16; c++) shx += g_fhx[c * (BB * NN) + i];
        float sct = 0.f;
        #pragma unroll
        for (int c = 0; c < 16; c++) sct += g_fct[c * (BB * NN) + i];
        float inv = __fdividef(1.0f, g_den[i >> 10]);
        out[i] = fast_tanh(shx + sct * inv);
        __syncthreads();
        if (tid == 0) {
            int old = atomicAdd(&g_ctr3, 1);
            if (old == 127) {            // last finisher: reset for next replay
                g_ctr0 = 0; g_ctr2 = 0; g_ctr3 = 0;
                g_flag0 = 0; g_flag2 = 0;
                __threadfence();
            }
        }
    }
}

// ---------------------------------------------------------------------------
extern "C" void kernel_launch(void* const* d_in, const int* in_sizes, int n_in,
                              void* d_out, int out_size)
{
    const float* decoder_hx      = (const float*)d_in[0];
    const float* encoder_outputs = (const float*)d_in[1];
    const float* encoder_feature = (const float*)d_in[2];
    const float* mask_tensor     = (const float*)d_in[3];
    const float* Ws_w            = (const float*)d_in[4];
    const float* Ws_b            = (const float*)d_in[5];
    const float* v_w             = (const float*)d_in[6];
    const float* v_b             = (const float*)d_in[7];
    const float* lin_w           = (const float*)d_in[8];
    const float* lin_b           = (const float*)d_in[9];
    float* out = (float*)d_out;

    // 1) gemm1 (dec partials + fhx) + in-kernel dec combine + accum zeroing
    kernelA<<<640, 256>>>(decoder_hx, Ws_w, lin_w, Ws_b);

    // 2) scores (streams 256MB)
    scores_kernel<<<dim3(TT / 16, BB), 256>>>(encoder_feature, v_w, v_b);

    // 3) content (streams 256MB): C=0 weights, atomic accumulation
    content_partial_kernel<<<dim3(NCH, BB), 256>>>(encoder_outputs, mask_tensor);

    // 4) gemm2 (fct) + in-kernel final combine + tanh + counter/flag reset
    kernelD<<<384, 256>>>(lin_w, lin_b, out);

    (void)in_sizes; (void)n_in; (void)out_size;
}

// round 15
// speedup vs baseline: 1.0207x; 1.0033x over previous
#include <cuda_runtime.h>
#include <cstdint>

#define TT 2048
#define BB 32
#define NN 1024
#define NCH 32   // 64-t chunks

// ---------------- scratch (device globals; no allocation allowed) ----------
__device__ float g_apart[16u * BB * NN];   // dec split-K partials
__device__ float g_fhx  [16u * BB * NN];   // hx @ lin_w[:,NN:] partials
__device__ float g_fct  [16u * BB * NN];   // content_raw @ lin_w[:,:NN] partials
__device__ float g_dec  [BB * NN];         // dec_feature (combined)
__device__ float g_scores[BB * TT];
__device__ float g_content[BB * NN];       // UNNORMALIZED content (atomics)
__device__ float g_den  [BB];              // softmax denominators (atomics)
__device__ float g_wstage[NN * NN];        // staged lin_w[:,0:NN] (L2-hot)
__device__ float g_hxsum[BB * NN];         // pre-reduced hx-half partials
__device__ int   g_ctr0, g_flag0;          // kernelA producer count / flag
__device__ int   g_ctr2, g_flag2;          // kernelD producer count / flag
__device__ int   g_ctr3;                   // kernelD consumer count (reset)

__device__ __forceinline__ float fast_tanh(float x) {      // precise (~1e-7)
    float e = __expf(2.0f * x);
    return 1.0f - __fdividef(2.0f, e + 1.0f);
}
__device__ __forceinline__ float tanh_mufu(float x) {      // MUFU.TANH, 1 op
    float y;
    asm("tanh.approx.f32 %0, %1;" : "=f"(y) : "f"(x));
    return y;
}

#define KC 64
#define QK (KC / 4)
#define PITCH (KC + 4)

// ---------------------------------------------------------------------------
// GEMM tile body: part[kc][b][n] = sum_{k in 64-chunk} S[b][k]*W[n][k]
// Tile 32b x 64n x 64k, thread tile 2b x 4n.
// ---------------------------------------------------------------------------
__device__ __forceinline__ void gemm_tile(
    const float* __restrict__ Sp, const float* __restrict__ Wp,
    int ws, int col0, int k0, int n0, float* outp,
    float* sS, float* sW, int tid)
{
    #pragma unroll
    for (int p = 0; p < 2; p++) {
        int i = tid + p * 256;
        int row = i >> 4, q = i & 15;
        float4 v = *(const float4*)&Sp[row * NN + k0 + q * 4];
        *(float4*)&sS[row * PITCH + q * 4] = v;
    }
    #pragma unroll
    for (int p = 0; p < 4; p++) {
        int i = tid + p * 256;
        int row = i >> 4, q = i & 15;
        float4 v = *(const float4*)&Wp[(size_t)(n0 + row) * ws + col0 + q * 4];
        *(float4*)&sW[row * PITCH + q * 4] = v;
    }
    __syncthreads();

    const int b0 = (tid & 15) * 2;
    const int nl = (tid >> 4) * 4;
    float acc[2][4];
    #pragma unroll
    for (int i = 0; i < 2; i++)
        #pragma unroll
        for (int j = 0; j < 4; j++) acc[i][j] = 0.f;

    const float* ps = sS + b0 * PITCH;
    const float* pw = sW + nl * PITCH;
    #pragma unroll 4
    for (int k4 = 0; k4 < QK; k4++) {
        float4 s[2], w[4];
        #pragma unroll
        for (int i = 0; i < 2; i++) s[i] = *(const float4*)(ps + i * PITCH + k4 * 4);
        #pragma unroll
        for (int j = 0; j < 4; j++) w[j] = *(const float4*)(pw + j * PITCH + k4 * 4);
        #pragma unroll
        for (int i = 0; i < 2; i++)
            #pragma unroll
            for (int j = 0; j < 4; j++)
                acc[i][j] += s[i].x * w[j].x + s[i].y * w[j].y
                           + s[i].z * w[j].z + s[i].w * w[j].w;
    }

    #pragma unroll
    for (int i = 0; i < 2; i++) {
        float4 r = make_float4(acc[i][0], acc[i][1], acc[i][2], acc[i][3]);
        *(float4*)&outp[(b0 + i) * NN + n0 + nl] = r;
    }
}

// Producer completion: count once; the 256th producer raises the flag.
__device__ __forceinline__ void signal_done(int* ctr, int* flag, int tid)
{
    __threadfence();
    __syncthreads();
    if (tid == 0) {
        int old = atomicAdd(ctr, 1);
        if (old == 255) {
            __threadfence();
            *(volatile int*)flag = 1;
        }
    }
}

// Consumer wait: plain volatile-load poll (no atomic-ALU contention).
__device__ __forceinline__ void wait_flag(int* flag, int tid, int* s_flag)
{
    if (tid == 0) {
        while (*(volatile int*)flag == 0) __nanosleep(1000);
        *s_flag = 1;
    }
    __syncthreads();
    __threadfence();   // acquire
}

// ---------------------------------------------------------------------------
// KERNEL A (640 blocks, all co-resident):
//   bid <256 : src0 gemm (hx @ Ws_w -> g_apart), signal ctr0/flag0
//   256..511 : src1 gemm (hx @ lin_w[:,NN:] -> g_fhx)
//   512..639 : zero g_content/g_den (overlapped), wait flag0,
//              g_dec = Ws_b + sum of 16 partials
// ---------------------------------------------------------------------------
__global__ __launch_bounds__(256) void kernelA(
    const float* __restrict__ hx,
    const float* __restrict__ Ws_w,
    const float* __restrict__ lin_w,
    const float* __restrict__ Ws_b)
{
    __shared__ float sS[32 * PITCH];
    __shared__ float sW[64 * PITCH];
    __shared__ int   s_flag;
    const int bid = blockIdx.x;
    const int tid = threadIdx.x;

    if (bid < 512) {
        const int rem = bid & 255;
        const int n0  = (rem & 15) * 64;
        const int k0  = (rem >> 4) * KC;
        if (bid < 256) {
            gemm_tile(hx, Ws_w, NN, k0, k0, n0,
                      g_apart + (size_t)(rem >> 4) * (BB * NN), sS, sW, tid);
            signal_done(&g_ctr0, &g_flag0, tid);
        } else {
            gemm_tile(hx, lin_w, 2 * NN, NN + k0, k0, n0,
                      g_fhx + (size_t)(rem >> 4) * (BB * NN), sS, sW, tid);
        }
    } else {
        const int i = (bid - 512) * 256 + tid;     // 0..32767
        g_content[i] = 0.f;
        if (i < BB) g_den[i] = 0.f;
        wait_flag(&g_flag0, tid, &s_flag);
        float s = Ws_b[i & (NN - 1)];
        #pragma unroll
        for (int c = 0; c < 16; c++) s += g_apart[c * (BB * NN) + i];
        g_dec[i] = s;
    }
}

// ---------------------------------------------------------------------------
// scores[b,t] = sum_n tanh(ef[t,b,n] + dec[b,n]) * v[n] + vb   (MUFU.TANH)
// ---------------------------------------------------------------------------
__global__ __launch_bounds__(256) void scores_kernel(
    const float* __restrict__ ef, const float* __restrict__ vw,
    const float* __restrict__ vb)
{
    const int b   = blockIdx.y;
    const int t0  = blockIdx.x * 16;
    const int tid = threadIdx.x;
    __shared__ float sred[16 * 256];

    float4 d = reinterpret_cast<const float4*>(g_dec + b * NN)[tid];
    float4 v = reinterpret_cast<const float4*>(vw)[tid];

    float pr[16];
    #pragma unroll
    for (int r = 0; r < 16; r++) {
        size_t row = ((size_t)(t0 + r) * BB + b) * NN;
        float4 x = __ldcs(&reinterpret_cast<const float4*>(ef + row)[tid]);
        pr[r] = tanh_mufu(x.x + d.x) * v.x
              + tanh_mufu(x.y + d.y) * v.y
              + tanh_mufu(x.z + d.z) * v.z
              + tanh_mufu(x.w + d.w) * v.w;
    }
    #pragma unroll
    for (int r = 0; r < 16; r++) sred[r * 256 + tid] = pr[r];
    __syncthreads();

    const int warp = tid >> 5, lane = tid & 31;
    #pragma unroll
    for (int rr = 0; rr < 2; rr++) {
        int r = warp * 2 + rr;
        float s = 0.f;
        #pragma unroll
        for (int j = 0; j < 8; j++) s += sred[r * 256 + lane + 32 * j];
        #pragma unroll
        for (int o = 16; o; o >>= 1) s += __shfl_xor_sync(0xffffffffu, s, o);
        if (lane == 0) g_scores[b * TT + t0 + r] = s + vb[0];
    }
}

// ---------------------------------------------------------------------------
// content kernel, grid (NCH+2, BB):
//   ch <NCH  : C=0 softmax weights + RED.ADD content (streams 256MB)
//   ch==NCH  : STAGE lin_w[:,0:NN] rows b*32..b*32+31 into g_wstage (L2-warm
//              for kernelD; overlapped with the DRAM stream)
//   ch==NCH+1: pre-reduce the 16 g_fhx partials into g_hxsum (128KB, L2-warm)
// ---------------------------------------------------------------------------
__global__ __launch_bounds__(256) void content_partial_kernel(
    const float* __restrict__ eo, const float* __restrict__ mask,
    const float* __restrict__ lin_w)
{
    const int b = blockIdx.y, ch = blockIdx.x, tid = threadIdx.x;

    if (ch == NCH) {          // stage 32 rows of lin_w low half (128KB/block)
        const int r0 = b * 32;
        for (int rr = 0; rr < 32; rr++) {
            const float4* src = reinterpret_cast<const float4*>(
                lin_w + (size_t)(r0 + rr) * (2 * NN));
            reinterpret_cast<float4*>(g_wstage + (size_t)(r0 + rr) * NN)[tid]
                = src[tid];
        }
        return;
    }
    if (ch == NCH + 1) {      // pre-reduce fhx partials (1KB-float4/block seg)
        const int i4 = b * 256 + tid;            // float4 index, 8192 total
        float4 s = make_float4(0.f, 0.f, 0.f, 0.f);
        #pragma unroll
        for (int c = 0; c < 16; c++) {
            float4 v = reinterpret_cast<const float4*>(g_fhx)[c * (BB * NN / 4) + i4];
            s.x += v.x; s.y += v.y; s.z += v.z; s.w += v.w;
        }
        reinterpret_cast<float4*>(g_hxsum)[i4] = s;
        return;
    }

    const int t0 = ch * 64;
    __shared__ float s_w[64];

    if (tid < 64) {
        float e = __expf(g_scores[b * TT + t0 + tid]);
        s_w[tid] = e * mask[b * TT + t0 + tid];
        #pragma unroll
        for (int o = 16; o; o >>= 1) e += __shfl_xor_sync(0xffffffffu, e, o);
        if ((tid & 31) == 0) atomicAdd(&g_den[b], e);
    }
    __syncthreads();

    float4 acc = make_float4(0.f, 0.f, 0.f, 0.f);
    size_t base = (((size_t)t0) * BB + b) * NN;
    #pragma unroll 4
    for (int r = 0; r < 64; r++) {
        float a = s_w[r];
        float4 x = __ldcs(&reinterpret_cast<const float4*>(eo + base + (size_t)r * BB * NN)[tid]);
        acc.x += a * x.x;  acc.y += a * x.y;
        acc.z += a * x.z;  acc.w += a * x.w;
    }
    float* dst = g_content + b * NN + tid * 4;
    atomicAdd(dst + 0, acc.x);
    atomicAdd(dst + 1, acc.y);
    atomicAdd(dst + 2, acc.z);
    atomicAdd(dst + 3, acc.w);
}

// ---------------------------------------------------------------------------
// KERNEL D (384 blocks, co-resident): ALL inputs L2-hot (staged/fresh).
//   bid <256 : fct gemm (g_content @ g_wstage -> g_fct), signal ctr2/flag2
//   256..383 : wait flag2; out = tanh(lin_b + g_hxsum + sum fct / den);
//              last finisher resets counters+flags for graph replay.
// Device globals referenced in DEVICE code only (host-side __device__-symbol
// args bind the zero ATS shadow on GB300 — R1/R2 bug).
// ---------------------------------------------------------------------------
__global__ __launch_bounds__(256) void kernelD(
    const float* __restrict__ lin_b,
    float* __restrict__ out)
{
    __shared__ float sS[32 * PITCH];
    __shared__ float sW[64 * PITCH];
    __shared__ int   s_flag;
    const int bid = blockIdx.x;
    const int tid = threadIdx.x;

    if (bid < 256) {
        const int n0 = (bid & 15) * 64;
        const int k0 = (bid >> 4) * KC;
        gemm_tile(g_content, g_wstage, NN, k0, k0, n0,
                  g_fct + (size_t)(bid >> 4) * (BB * NN), sS, sW, tid);
        signal_done(&g_ctr2, &g_flag2, tid);
    } else {
        wait_flag(&g_flag2, tid, &s_flag);
        const int i = (bid - 256) * 256 + tid;
        float shx = g_hxsum[i] + lin_b[i & (NN - 1)];
        float sct = 0.f;
        #pragma unroll
        for (int c = 0; c < 16; c++) sct += g_fct[c * (BB * NN) + i];
        float inv = __fdividef(1.0f, g_den[i >> 10]);
        out[i] = fast_tanh(shx + sct * inv);
        __syncthreads();
        if (tid == 0) {
            int old = atomicAdd(&g_ctr3, 1);
            if (old == 127) {            // last finisher: reset for next replay
                g_ctr0 = 0; g_ctr2 = 0; g_ctr3 = 0;
                g_flag0 = 0; g_flag2 = 0;
                __threadfence();
            }
        }
    }
}

// ---------------------------------------------------------------------------
extern "C" void kernel_launch(void* const* d_in, const int* in_sizes, int n_in,
                              void* d_out, int out_size)
{
    const float* decoder_hx      = (const float*)d_in[0];
    const float* encoder_outputs = (const float*)d_in[1];
    const float* encoder_feature = (const float*)d_in[2];
    const float* mask_tensor     = (const float*)d_in[3];
    const float* Ws_w            = (const float*)d_in[4];
    const float* Ws_b            = (const float*)d_in[5];
    const float* v_w             = (const float*)d_in[6];
    const float* v_b             = (const float*)d_in[7];
    const float* lin_w           = (const float*)d_in[8];
    const float* lin_b           = (const float*)d_in[9];
    float* out = (float*)d_out;

    // 1) gemm1 (dec partials + fhx) + in-kernel dec combine + accum zeroing
    kernelA<<<640, 256>>>(decoder_hx, Ws_w, lin_w, Ws_b);

    // 2) scores (streams 256MB)
    scores_kernel<<<dim3(TT / 16, BB), 256>>>(encoder_feature, v_w, v_b);

    // 3) content stream + lin_w staging + fhx pre-reduction (overlapped)
    content_partial_kernel<<<dim3(NCH + 2, BB), 256>>>(
        encoder_outputs, mask_tensor, lin_w);

    // 4) gemm2 on L2-hot staged data + output tanh + counter/flag reset
    kernelD<<<384, 256>>>(lin_b, out);

    (void)in_sizes; (void)n_in; (void)out_size;
}

// round 16
// speedup vs baseline: 1.0499x; 1.0286x over previous
#include <cuda_runtime.h>
#include <cstdint>

#define TT 2048
#define BB 32
#define NN 1024
#define NCH 32   // 64-t chunks

// ---------------- scratch (device globals; no allocation allowed) ----------
// All accumulators are zero on first use (static zero-init) and re-zeroed by
// combine_out at the END of each graph replay.
__device__ float g_dec_acc[BB * NN];   // dec gemm accumulator (no bias)
__device__ float g_hxacc [BB * NN];    // hx @ lin_w[:,NN:2NN] accumulator
__device__ float g_oacc  [BB * NN];    // content @ lin_w[:,0:NN] accumulator
__device__ float g_scores[BB * TT];
__device__ float g_content[BB * NN];   // UNNORMALIZED content (atomics)
__device__ float g_den   [BB];         // softmax denominators (atomics)

__device__ __forceinline__ float fast_tanh(float x) {      // precise (~1e-7)
    float e = __expf(2.0f * x);
    return 1.0f - __fdividef(2.0f, e + 1.0f);
}
__device__ __forceinline__ float tanh_mufu(float x) {      // MUFU.TANH, 1 op
    float y;
    asm("tanh.approx.f32 %0, %1;" : "=f"(y) : "f"(x));
    return y;
}

#define KC 64
#define QK (KC / 4)
#define PITCH (KC + 4)

// ---------------------------------------------------------------------------
// Skinny GEMM with RED.ADD output: acc[b,n] += sum_{k in chunk} S[b,k]*W[n,k]
// Tile 32b x 64n x 64k, thread tile 2b x 4n (~40 regs; 256+ blocks/launch for
// latency hiding — the R10 lesson).
// src 0: hx @ Ws_w            +-> g_dec_acc
// src 1: hx @ lin_w[:,NN:2NN] +-> g_hxacc    (same launch via blockIdx.z)
// src 2: (g_content / g_den) @ lin_w[:,0:NN] +-> g_oacc
// Device globals referenced in DEVICE code only (host-side __device__-symbol
// args bind the zero ATS shadow on GB300 — the R1/R2 bug).
// ---------------------------------------------------------------------------
__global__ __launch_bounds__(256, 2) void gemm_skinny(
    const float* __restrict__ hx,
    const float* __restrict__ Ws_w,
    const float* __restrict__ lin_w,
    int src_base)
{
    __shared__ float sS[32 * PITCH];
    __shared__ float sW[64 * PITCH];
    const int tid = threadIdx.x;
    const int n0  = blockIdx.x * 64;
    const int k0  = blockIdx.y * KC;
    const int src = src_base + blockIdx.z;

    const float* Sp; const float* Wp; int ws; int col0; float* accp;
    if (src == 0)      { Sp = hx;        Wp = Ws_w;  ws = NN;     col0 = k0;      accp = g_dec_acc; }
    else if (src == 1) { Sp = hx;        Wp = lin_w; ws = 2 * NN; col0 = NN + k0; accp = g_hxacc; }
    else               { Sp = g_content; Wp = lin_w; ws = 2 * NN; col0 = k0;      accp = g_oacc; }

    // S tile: 32 x 64 floats (normalize content rows by 1/g_den for src2)
    #pragma unroll
    for (int p = 0; p < 2; p++) {
        int i = tid + p * 256;
        int row = i >> 4, q = i & 15;
        float4 v = *(const float4*)&Sp[row * NN + k0 + q * 4];
        if (src == 2) {
            float inv = __fdividef(1.0f, g_den[row]);
            v.x *= inv; v.y *= inv; v.z *= inv; v.w *= inv;
        }
        *(float4*)&sS[row * PITCH + q * 4] = v;
    }
    // W tile: 64 x 64 floats
    #pragma unroll
    for (int p = 0; p < 4; p++) {
        int i = tid + p * 256;
        int row = i >> 4, q = i & 15;
        float4 v = *(const float4*)&Wp[(size_t)(n0 + row) * ws + col0 + q * 4];
        *(float4*)&sW[row * PITCH + q * 4] = v;
    }
    __syncthreads();

    const int b0 = (tid & 15) * 2;
    const int nl = (tid >> 4) * 4;
    float acc[2][4];
    #pragma unroll
    for (int i = 0; i < 2; i++)
        #pragma unroll
        for (int j = 0; j < 4; j++) acc[i][j] = 0.f;

    const float* ps = sS + b0 * PITCH;
    const float* pw = sW + nl * PITCH;
    #pragma unroll 4
    for (int k4 = 0; k4 < QK; k4++) {
        float4 s[2], w[4];
        #pragma unroll
        for (int i = 0; i < 2; i++) s[i] = *(const float4*)(ps + i * PITCH + k4 * 4);
        #pragma unroll
        for (int j = 0; j < 4; j++) w[j] = *(const float4*)(pw + j * PITCH + k4 * 4);
        #pragma unroll
        for (int i = 0; i < 2; i++)
            #pragma unroll
            for (int j = 0; j < 4; j++)
                acc[i][j] += s[i].x * w[j].x + s[i].y * w[j].y
                           + s[i].z * w[j].z + s[i].w * w[j].w;
    }

    // RED.ADD (spread addresses, ~0.85 cyc/lane, no read-back)
    #pragma unroll
    for (int i = 0; i < 2; i++) {
        float* dst = accp + (b0 + i) * NN + n0 + nl;
        #pragma unroll
        for (int j = 0; j < 4; j++) atomicAdd(dst + j, acc[i][j]);
    }
}

// ---------------------------------------------------------------------------
// scores[b,t] = sum_n tanh(ef[t,b,n] + dec_acc[b,n] + Ws_b[n]) * v[n] + vb
// (MUFU.TANH; combine_dec folded into the d-vector load)
// ---------------------------------------------------------------------------
__global__ __launch_bounds__(256) void scores_kernel(
    const float* __restrict__ ef, const float* __restrict__ vw,
    const float* __restrict__ vb, const float* __restrict__ Ws_b)
{
    const int b   = blockIdx.y;
    const int t0  = blockIdx.x * 16;
    const int tid = threadIdx.x;
    __shared__ float sred[16 * 256];

    float4 d  = reinterpret_cast<const float4*>(g_dec_acc + b * NN)[tid];
    float4 bb = reinterpret_cast<const float4*>(Ws_b)[tid];
    d.x += bb.x; d.y += bb.y; d.z += bb.z; d.w += bb.w;
    float4 v = reinterpret_cast<const float4*>(vw)[tid];

    float pr[16];
    #pragma unroll
    for (int r = 0; r < 16; r++) {
        size_t row = ((size_t)(t0 + r) * BB + b) * NN;
        float4 x = __ldcs(&reinterpret_cast<const float4*>(ef + row)[tid]);
        pr[r] = tanh_mufu(x.x + d.x) * v.x
              + tanh_mufu(x.y + d.y) * v.y
              + tanh_mufu(x.z + d.z) * v.z
              + tanh_mufu(x.w + d.w) * v.w;
    }
    #pragma unroll
    for (int r = 0; r < 16; r++) sred[r * 256 + tid] = pr[r];
    __syncthreads();

    const int warp = tid >> 5, lane = tid & 31;
    #pragma unroll
    for (int rr = 0; rr < 2; rr++) {
        int r = warp * 2 + rr;
        float s = 0.f;
        #pragma unroll
        for (int j = 0; j < 8; j++) s += sred[r * 256 + lane + 32 * j];
        #pragma unroll
        for (int o = 16; o; o >>= 1) s += __shfl_xor_sync(0xffffffffu, s, o);
        if (lane == 0) g_scores[b * TT + t0 + r] = s + vb[0];
    }
}

// ---------------------------------------------------------------------------
// content (C=0 exponentials — scores O(+-5) by construction):
//   w_t = exp(s_t)*mask_t ; g_den[b] += sum exp(s_t)
//   g_content[b][:] += sum_t w_t * eo[t,b,:]    (RED.ADD)
// ---------------------------------------------------------------------------
__global__ __launch_bounds__(256) void content_partial_kernel(
    const float* __restrict__ eo, const float* __restrict__ mask)
{
    const int b = blockIdx.y, ch = blockIdx.x, tid = threadIdx.x;
    const int t0 = ch * 64;
    __shared__ float s_w[64];

    if (tid < 64) {
        float e = __expf(g_scores[b * TT + t0 + tid]);
        s_w[tid] = e * mask[b * TT + t0 + tid];
        #pragma unroll
        for (int o = 16; o; o >>= 1) e += __shfl_xor_sync(0xffffffffu, e, o);
        if ((tid & 31) == 0) atomicAdd(&g_den[b], e);
    }
    __syncthreads();

    float4 acc = make_float4(0.f, 0.f, 0.f, 0.f);
    size_t base = (((size_t)t0) * BB + b) * NN;
    #pragma unroll 4
    for (int r = 0; r < 64; r++) {
        float a = s_w[r];
        float4 x = __ldcs(&reinterpret_cast<const float4*>(eo + base + (size_t)r * BB * NN)[tid]);
        acc.x += a * x.x;  acc.y += a * x.y;
        acc.z += a * x.z;  acc.w += a * x.w;
    }
    float* dst = g_content + b * NN + tid * 4;
    atomicAdd(dst + 0, acc.x);
    atomicAdd(dst + 1, acc.y);
    atomicAdd(dst + 2, acc.z);
    atomicAdd(dst + 3, acc.w);
}

// ---------------------------------------------------------------------------
// combine_out: out = tanh(lin_b + g_hxacc + g_oacc)  (g_oacc pre-normalized
// by gemm2). Then re-zero ALL accumulators for the next graph replay —
// end-of-graph zeroing keeps every replay identical with no extra launch.
// ---------------------------------------------------------------------------
__global__ __launch_bounds__(256) void combine_out(
    const float* __restrict__ lin_b, float* __restrict__ out)
{
    int i = blockIdx.x * 256 + threadIdx.x;
    float s = lin_b[i & (NN - 1)] + g_hxacc[i] + g_oacc[i];
    out[i] = fast_tanh(s);
    // reset for next replay (first run uses static zero-init)
    g_dec_acc[i] = 0.f;
    g_hxacc[i]   = 0.f;
    g_oacc[i]    = 0.f;
    g_content[i] = 0.f;
    if (i < BB) g_den[i] = 0.f;
}

// ---------------------------------------------------------------------------
extern "C" void kernel_launch(void* const* d_in, const int* in_sizes, int n_in,
                              void* d_out, int out_size)
{
    const float* decoder_hx      = (const float*)d_in[0];
    const float* encoder_outputs = (const float*)d_in[1];
    const float* encoder_feature = (const float*)d_in[2];
    const float* mask_tensor     = (const float*)d_in[3];
    const float* Ws_w            = (const float*)d_in[4];
    const float* Ws_b            = (const float*)d_in[5];
    const float* v_w             = (const float*)d_in[6];
    const float* v_b             = (const float*)d_in[7];
    const float* lin_w           = (const float*)d_in[8];
    const float* lin_b           = (const float*)d_in[9];
    float* out = (float*)d_out;

    // 1) dec gemm (src0 -> g_dec_acc) + hx-half gemm (src1 -> g_hxacc)
    gemm_skinny<<<dim3(NN / 64, NN / KC, 2), 256>>>(decoder_hx, Ws_w, lin_w, 0);

    // 2) scores (streams 256MB); Ws_b + dec combine folded in
    scores_kernel<<<dim3(TT / 16, BB), 256>>>(encoder_feature, v_w, v_b, Ws_b);

    // 3) content (streams 256MB): C=0 weights, atomic accumulation
    content_partial_kernel<<<dim3(NCH, BB), 256>>>(encoder_outputs, mask_tensor);

    // 4) content gemm (src2, normalized by g_den -> g_oacc)
    gemm_skinny<<<dim3(NN / 64, NN / KC, 1), 256>>>(decoder_hx, Ws_w, lin_w, 2);

    // 5) output + accumulator re-zeroing for next replay
    combine_out<<<(BB * NN) / 256, 256>>>(lin_b, out);

    (void)in_sizes; (void)n_in; (void)out_size;
}